// round 2
// baseline (speedup 1.0000x reference)
#include <cuda_runtime.h>
#include <cuda_bf16.h>

// ---------------------------------------------------------------------------
// PointGenerator: X_world = (E_ @ n2r @ K_^-1) @ [x*d, y*d, d, 1]
//
// Per-camera matrix M (3x4), derived analytically:
//   M[i][0] =  E[i][0]/f
//   M[i][1] = -E[i][1]/f
//   M[i][2] = (-E[i][0]*cx + E[i][1]*cy)/f - E[i][2]
//   M[i][3] =  E[i][3]
// Output row 3 is identically [0,0,0,1] -> w component = 1.
// image_coords[y,x]-0.5 == (float)y,(float)x exactly (ints + 0.5 - 0.5).
// ---------------------------------------------------------------------------

#define MAX_CAMS 256

// Scratch for precomputed camera matrices (no cudaMalloc allowed).
__device__ float4 g_camM[MAX_CAMS * 3];

__global__ void precompute_cams_kernel(const float* __restrict__ cam2world, // [C,3,4]
                                       const float* __restrict__ intr,      // [C,3,3]
                                       int num_cams) {
    int c = blockIdx.x * blockDim.x + threadIdx.x;
    if (c >= num_cams) return;
    const float* E = cam2world + c * 12;
    const float* K = intr + c * 9;
    // K = [[f,0,cx],[0,f,cy],[0,0,1]]
    double f  = (double)K[0];
    double cx = (double)K[2];
    double cy = (double)K[5];
    double invf = 1.0 / f;
#pragma unroll
    for (int i = 0; i < 3; i++) {
        double e0 = (double)E[i * 4 + 0];
        double e1 = (double)E[i * 4 + 1];
        double e2 = (double)E[i * 4 + 2];
        double e3 = (double)E[i * 4 + 3];
        float4 r;
        r.x = (float)(e0 * invf);
        r.y = (float)(-e1 * invf);
        r.z = (float)((-e0 * cx + e1 * cy) * invf - e2);
        r.w = (float)e3;
        g_camM[c * 3 + i] = r;
    }
}

__global__ void __launch_bounds__(256)
point_gen_kernel(const int4* __restrict__ pidx4,   // point_indices as int4 (3 per 4 points)
                 const float4* __restrict__ depth4, // depth as float4
                 float4* __restrict__ out4,         // output rows as float4
                 int nquads, int cam_words) {
    extern __shared__ float4 s_cam[]; // num_cams * 3 float4
    for (int i = threadIdx.x; i < cam_words; i += blockDim.x)
        s_cam[i] = g_camM[i];
    __syncthreads();

    int t = blockIdx.x * blockDim.x + threadIdx.x;
    if (t >= nquads) return;

    // 4 points = 12 ints = 3 aligned int4 loads
    int4 a  = pidx4[3 * t + 0];
    int4 b  = pidx4[3 * t + 1];
    int4 cc = pidx4[3 * t + 2];
    float4 d4 = depth4[t];

    int   cs[4] = {a.x, a.w, b.z, cc.y};
    int   ys[4] = {a.y, b.x, b.w, cc.z};
    int   xs[4] = {a.z, b.y, cc.x, cc.w};
    float ds[4] = {d4.x, d4.y, d4.z, d4.w};

#pragma unroll
    for (int j = 0; j < 4; j++) {
        float dd = ds[j];
        float xd = (float)xs[j] * dd;
        float yd = (float)ys[j] * dd;
        const float4* M = &s_cam[cs[j] * 3];
        float4 r0 = M[0];
        float4 r1 = M[1];
        float4 r2 = M[2];
        float4 o;
        o.x = fmaf(r0.x, xd, fmaf(r0.y, yd, fmaf(r0.z, dd, r0.w)));
        o.y = fmaf(r1.x, xd, fmaf(r1.y, yd, fmaf(r1.z, dd, r1.w)));
        o.z = fmaf(r2.x, xd, fmaf(r2.y, yd, fmaf(r2.z, dd, r2.w)));
        o.w = 1.0f;
        out4[4 * t + j] = o;
    }
}

// Scalar tail (npoints not divisible by 4) — not expected here (2M % 4 == 0),
// but kept for safety.
__global__ void point_gen_tail_kernel(const int* __restrict__ pidx,
                                      const float* __restrict__ depth,
                                      float4* __restrict__ out4,
                                      int start, int npoints) {
    int p = start + blockIdx.x * blockDim.x + threadIdx.x;
    if (p >= npoints) return;
    int c = pidx[3 * p + 0];
    int y = pidx[3 * p + 1];
    int x = pidx[3 * p + 2];
    float dd = depth[p];
    float xd = (float)x * dd;
    float yd = (float)y * dd;
    float4 r0 = g_camM[c * 3 + 0];
    float4 r1 = g_camM[c * 3 + 1];
    float4 r2 = g_camM[c * 3 + 2];
    float4 o;
    o.x = fmaf(r0.x, xd, fmaf(r0.y, yd, fmaf(r0.z, dd, r0.w)));
    o.y = fmaf(r1.x, xd, fmaf(r1.y, yd, fmaf(r1.z, dd, r1.w)));
    o.z = fmaf(r2.x, xd, fmaf(r2.y, yd, fmaf(r2.z, dd, r2.w)));
    o.w = 1.0f;
    out4[p] = o;
}

extern "C" void kernel_launch(void* const* d_in, const int* in_sizes, int n_in,
                              void* d_out, int out_size) {
    // metadata order: point_indices[N,3] i32, depth[N,1] f32, image_coords (unused),
    //                 camera_to_worlds[C,3,4] f32, intrinsics[C,3,3] f32
    const int*   pidx  = (const int*)d_in[0];
    const float* depth = (const float*)d_in[1];
    const float* c2w   = (const float*)d_in[3];
    const float* intr  = (const float*)d_in[4];
    float*       out   = (float*)d_out;

    int npoints  = in_sizes[0] / 3;
    int num_cams = in_sizes[3] / 12;
    if (num_cams > MAX_CAMS) num_cams = MAX_CAMS;

    // 1) per-camera matrices (tiny)
    precompute_cams_kernel<<<(num_cams + 127) / 128, 128>>>(c2w, intr, num_cams);

    // 2) main pass: 4 points per thread, fully vectorized
    int nquads = npoints / 4;
    int cam_words = num_cams * 3;
    size_t smem = (size_t)cam_words * sizeof(float4);
    if (nquads > 0) {
        int threads = 256;
        int blocks = (nquads + threads - 1) / threads;
        point_gen_kernel<<<blocks, threads, smem>>>(
            (const int4*)pidx, (const float4*)depth, (float4*)out, nquads, cam_words);
    }

    // 3) tail
    int rem = npoints - nquads * 4;
    if (rem > 0) {
        point_gen_tail_kernel<<<1, 128>>>(pidx, depth, (float4*)out, nquads * 4, npoints);
    }
}